// round 13
// baseline (speedup 1.0000x reference)
#include <cuda_runtime.h>
#include <math.h>

#define Lr 1024
#define Br 32
#define Dr 256
#define LAMf 0.2f
#define NR (Lr*Br)

// Scratch (device globals, zero-initialized). Batch-major r = b*Lr + i.
__device__ float g_Kn[NR*5];     // K[i,d] * invS[i]
__device__ float g_En[NR];       // E[i]  * invS[i]
__device__ int   g_cnt[Br];      // per-batch arrival counters (reset by epilogue)

typedef unsigned long long u64;

__device__ __forceinline__ u64 ffma2(u64 a, u64 b, u64 c) {
    u64 d;
    asm("fma.rn.f32x2 %0, %1, %2, %3;" : "=l"(d) : "l"(a), "l"(b), "l"(c));
    return d;
}
__device__ __forceinline__ float unpack_sum(u64 a) {
    float2 f = *reinterpret_cast<float2*>(&a);
    return f.x + f.y;
}

// Single kernel: 2048 band blocks + 32 epilogue blocks (scheduled last).
__global__ void __launch_bounds__(512) kall(const float* __restrict__ m1,
                                            const float* __restrict__ m2,
                                            const int* __restrict__ lengths,
                                            float* __restrict__ out) {
    // Union of band (tiny) and epilogue (26 KB) shared state; threads bind occupancy, not smem.
    __shared__ float sh_K[Lr*5];     // epilogue: staged Kn
    __shared__ float sh_t[Lr];
    __shared__ float sh_c[512];
    float* sh_invny = sh_t;          // band reuses first 20 floats

    int tid = threadIdx.x;
    int bid = blockIdx.x;

    if (bid < 2048) {
        // ======================= BAND BLOCK (R12 math) =======================
        int w    = tid >> 5, lane = tid & 31;
        int b    = bid & 31;
        int i0   = (bid >> 5) * 16;
        int l    = __ldg(lengths + b);
        int base = b * Lr;

        // phase 1: 20 y inverse norms
        {
            float ss[2];
            #pragma unroll
            for (int k = 0; k < 2; k++) {
                int job = w + k*16;
                u64 acc = 0ull;
                if (job < 20) {
                    int row = i0 - 2 + job;
                    if (row >= 0 && row < l) {
                        const ulonglong2* p = (const ulonglong2*)(m2 + ((size_t)(row*Br + b)) * Dr);
                        ulonglong2 a = p[lane], c = p[lane + 32];
                        acc = ffma2(a.x, a.x, acc);
                        acc = ffma2(a.y, a.y, acc);
                        acc = ffma2(c.x, c.x, acc);
                        acc = ffma2(c.y, c.y, acc);
                    }
                }
                ss[k] = unpack_sum(acc);
            }
            #pragma unroll
            for (int o = 16; o; o >>= 1) {
                #pragma unroll
                for (int k = 0; k < 2; k++) ss[k] += __shfl_xor_sync(0xffffffffu, ss[k], o);
            }
            if (lane == 0) {
                #pragma unroll
                for (int k = 0; k < 2; k++) {
                    int job = w + k*16;
                    if (job < 20)
                        sh_invny[job] = (ss[k] > 0.0f) ? (1.0f / fmaxf(sqrtf(ss[k]), 1e-5f)) : 0.0f;
                }
            }
        }
        __syncthreads();

        // phase 2: warp w owns row i = i0 + w
        int i = i0 + w;
        if (i < l) {
            const ulonglong2* xp = (const ulonglong2*)(m1 + ((size_t)(i*Br + b)) * Dr);
            ulonglong2 xa = xp[lane], xb = xp[lane + 32];
            u64 pacc[6];
            pacc[0] = ffma2(xa.x, xa.x, 0ull);
            pacc[0] = ffma2(xa.y, xa.y, pacc[0]);
            pacc[0] = ffma2(xb.x, xb.x, pacc[0]);
            pacc[0] = ffma2(xb.y, xb.y, pacc[0]);
            #pragma unroll
            for (int d = 0; d < 5; d++) {
                int j = i + d - 2;
                u64 acc = 0ull;
                if (j >= 0 && j < l) {
                    const ulonglong2* yp = (const ulonglong2*)(m2 + ((size_t)(j*Br + b)) * Dr);
                    ulonglong2 ya = yp[lane], yb = yp[lane + 32];
                    acc = ffma2(xa.x, ya.x, acc);
                    acc = ffma2(xa.y, ya.y, acc);
                    acc = ffma2(xb.x, yb.x, acc);
                    acc = ffma2(xb.y, yb.y, acc);
                }
                pacc[d + 1] = acc;
            }
            float s[6];
            #pragma unroll
            for (int q = 0; q < 6; q++) s[q] = unpack_sum(pacc[q]);
            #pragma unroll
            for (int o = 16; o; o >>= 1) {
                #pragma unroll
                for (int q = 0; q < 6; q++) s[q] += __shfl_xor_sync(0xffffffffu, s[q], o);
            }
            if (lane == 0) {
                float invnx = 1.0f / fmaxf(sqrtf(s[0]), 1e-5f);
                float S = 0.0f, E = 0.0f, Ks[5];
                #pragma unroll
                for (int d = 0; d < 5; d++) {
                    int j = i + d - 2;
                    float Kv = 0.0f;
                    if (j >= 0 && j < l) {
                        float Mv = 1.0f - s[d+1] * invnx * sh_invny[w + d];
                        Kv = __expf(-LAMf * Mv);
                        E += Kv * Mv;
                    }
                    Ks[d] = Kv; S += Kv;
                }
                float invS = 1.0f / S;
                int rr = base + i;
                g_En[rr] = E * invS;
                #pragma unroll
                for (int d = 0; d < 5; d++) g_Kn[rr*5 + d] = Ks[d] * invS;
                __threadfence();               // release this row's stores
            }
        }
        __syncthreads();
        if (tid == 0) atomicAdd(&g_cnt[b], 1);
        return;
    }

    // ======================= EPILOGUE BLOCK (batch b) =======================
    int b = bid - 2048;
    int l = __ldg(lengths + b);
    int base = b * Lr;

    if (tid == 0) {
        volatile int* cnt = (volatile int*)&g_cnt[b];
        while (*cnt != 64) __nanosleep(64);
        g_cnt[b] = 0;                          // reset for next graph replay
        __threadfence();                       // acquire
    }
    __syncthreads();

    // stage Kn (L2-direct reads) + prefetch En
    float Ev0 = __ldcg(g_En + base + tid);
    float Ev1 = __ldcg(g_En + base + tid + 512);
    {
        const float4* Ksrc = (const float4*)(g_Kn + (size_t)base * 5);
        float4* Kdst = (float4*)sh_K;
        #pragma unroll
        for (int k = 0; k < 3; k++) {
            int idx = tid + k*512;
            if (idx < Lr*5/4) Kdst[idx] = __ldcg(Ksrc + idx);
        }
    }
    __syncthreads();

    // t[j] + cost terms for rows tid and tid+512
    float acc = 0.0f;
    #pragma unroll
    for (int half = 0; half < 2; half++) {
        int j = tid + half*512;
        float t = 1.0f;
        if (j < l) {
            t = 0.0f;
            #pragma unroll
            for (int dd = 0; dd < 5; dd++) {
                int i = j + dd - 2;
                if (i >= 0 && i < l)
                    t += sh_K[i*5 + (4 - dd)];
            }
            acc += (half ? Ev1 : Ev0) / ((float)l * t);
        }
        sh_t[j] = t;
    }
    __syncthreads();

    // band scatter
    #pragma unroll
    for (int half = 0; half < 2; half++) {
        int j = tid + half*512;
        if (j < l) {
            float rt = 1.0f / sh_t[j];
            float* Po = out + (size_t)b * Lr * Lr + (size_t)j * Lr;
            #pragma unroll
            for (int d = 0; d < 5; d++) {
                int jj = j + d - 2;
                if (jj >= 0 && jj < l)
                    Po[jj] = sh_K[j*5 + d] * sh_t[jj] * rt;
            }
        }
    }

    // cost reduction (512)
    sh_c[tid] = acc;
    __syncthreads();
    #pragma unroll
    for (int s = 256; s; s >>= 1) {
        if (tid < s) sh_c[tid] += sh_c[tid + s];
        __syncthreads();
    }
    if (tid == 0) out[(size_t)Br * Lr * Lr + b] = sh_c[0];
}

extern "C" void kernel_launch(void* const* d_in, const int* in_sizes, int n_in,
                              void* d_out, int out_size) {
    const float* m1      = (const float*)d_in[0];
    const float* m2      = (const float*)d_in[1];
    const int*   lengths = (const int*)d_in[2];
    float* out = (float*)d_out;

    kall<<<2048 + Br, 512>>>(m1, m2, lengths, out);   // band + spin-wait epilogue, one launch
}

// round 14
// speedup vs baseline: 1.1892x; 1.1892x over previous
#include <cuda_runtime.h>
#include <math.h>

#define Lr 1024
#define Br 32
#define Dr 256
#define LAMf 0.2f
#define NR (Lr*Br)

// Scratch (device globals, zero-initialized). Batch-major r = b*Lr + i.
__device__ float g_Kn[NR*5];     // K[i,d] * invS[i]
__device__ float g_En[NR];       // E[i]  * invS[i]

typedef unsigned long long u64;

__device__ __forceinline__ u64 ffma2(u64 a, u64 b, u64 c) {
    u64 d;
    asm("fma.rn.f32x2 %0, %1, %2, %3;" : "=l"(d) : "l"(a), "l"(b), "l"(c));
    return d;
}
__device__ __forceinline__ float unpack_sum(u64 a) {
    float2 f = *reinterpret_cast<float2*>(&a);
    return f.x + f.y;
}

// ---------------------------------------------------------------- band kernel
// 2048 batch-pure blocks x 512 threads; warp w owns row i = i0 + w.
// y-norm of the d=2 row rides in the dot butterfly (7th accumulator);
// 4 edge-row norms via a tiny 4-warp mini-pass. Tail is lane-parallel.
__global__ void __launch_bounds__(512) kband(const float* __restrict__ m1,
                                             const float* __restrict__ m2,
                                             const int* __restrict__ lengths) {
    __shared__ float sh_invny[20];   // 1/||y_{i0-2+k}||, k = 0..19

    int tid  = threadIdx.x;
    int w    = tid >> 5, lane = tid & 31;
    int b    = blockIdx.x & 31;
    int i0   = (blockIdx.x >> 5) * 16;
    int l    = __ldg(lengths + b);
    int base = b * Lr;
    int i    = i0 + w;

    // ---- main: x load + 5 dots + xx + yy(d=2), one 7-wide butterfly ----
    float s[7];
    if (i < l) {
        const ulonglong2* xp = (const ulonglong2*)(m1 + ((size_t)(i*Br + b)) * Dr);
        ulonglong2 xa = xp[lane], xb = xp[lane + 32];
        u64 pacc[7];
        pacc[0] = ffma2(xa.x, xa.x, 0ull);
        pacc[0] = ffma2(xa.y, xa.y, pacc[0]);
        pacc[0] = ffma2(xb.x, xb.x, pacc[0]);
        pacc[0] = ffma2(xb.y, xb.y, pacc[0]);
        pacc[6] = 0ull;
        #pragma unroll
        for (int d = 0; d < 5; d++) {
            int j = i + d - 2;
            u64 acc = 0ull;
            if (j >= 0 && j < l) {
                const ulonglong2* yp = (const ulonglong2*)(m2 + ((size_t)(j*Br + b)) * Dr);
                ulonglong2 ya = yp[lane], yb = yp[lane + 32];
                acc = ffma2(xa.x, ya.x, acc);
                acc = ffma2(xa.y, ya.y, acc);
                acc = ffma2(xb.x, yb.x, acc);
                acc = ffma2(xb.y, yb.y, acc);
                if (d == 2) {                       // own y row: norm for free
                    u64 yy = ffma2(ya.x, ya.x, 0ull);
                    yy = ffma2(ya.y, ya.y, yy);
                    yy = ffma2(yb.x, yb.x, yy);
                    yy = ffma2(yb.y, yb.y, yy);
                    pacc[6] = yy;
                }
            }
            pacc[d + 1] = acc;
        }
        #pragma unroll
        for (int q = 0; q < 7; q++) s[q] = unpack_sum(pacc[q]);
        #pragma unroll
        for (int o = 16; o; o >>= 1) {
            #pragma unroll
            for (int q = 0; q < 7; q++) s[q] += __shfl_xor_sync(0xffffffffu, s[q], o);
        }
        if (lane == 0)
            sh_invny[w + 2] = 1.0f / fmaxf(sqrtf(s[6]), 1e-5f);   // row i0+w
    }

    // ---- mini-pass: 4 edge y-norm rows by warps 0-3 ----
    if (w < 4) {
        int eidx = (w < 2) ? w : (16 + w);             // sh slots 0,1,18,19
        int row  = i0 - 2 + eidx;
        float ss = 0.0f;
        if (row >= 0 && row < l) {
            const ulonglong2* p = (const ulonglong2*)(m2 + ((size_t)(row*Br + b)) * Dr);
            ulonglong2 a = p[lane], c = p[lane + 32];
            u64 acc = ffma2(a.x, a.x, 0ull);
            acc = ffma2(a.y, a.y, acc);
            acc = ffma2(c.x, c.x, acc);
            acc = ffma2(c.y, c.y, acc);
            ss = unpack_sum(acc);
        }
        #pragma unroll
        for (int o = 16; o; o >>= 1) ss += __shfl_xor_sync(0xffffffffu, ss, o);
        if (lane == 0)
            sh_invny[eidx] = (ss > 0.0f) ? (1.0f / fmaxf(sqrtf(ss), 1e-5f)) : 0.0f;
    }
    __syncthreads();

    // ---- lane-parallel tail: lanes 0-4 handle d = lane ----
    if (i < l) {
        float invnx = 1.0f / fmaxf(sqrtf(s[0]), 1e-5f);
        int d = lane;
        float Kv = 0.0f, Ev = 0.0f;
        if (d < 5) {
            int j = i + d - 2;
            if (j >= 0 && j < l) {
                float Mv = 1.0f - s[d + 1] * invnx * sh_invny[w + d];
                Kv = __expf(-LAMf * Mv);
                Ev = Kv * Mv;
            }
        }
        float S = Kv, E = Ev;
        #pragma unroll
        for (int o = 4; o; o >>= 1) {                  // 8-lane butterfly (lanes 5-7 hold 0)
            S += __shfl_xor_sync(0xffffffffu, S, o);
            E += __shfl_xor_sync(0xffffffffu, E, o);
        }
        float invS = 1.0f / S;
        int rr = base + i;
        if (lane < 5) g_Kn[rr*5 + lane] = Kv * invS;   // one 32B-sector wavefront
        if (lane == 0) g_En[rr] = E * invS;
    }
}

// ---------------------------------------------------------------- t + cost + band scatter (R12, verified)
__global__ void __launch_bounds__(1024) ktc(const int* __restrict__ lengths,
                                            float* __restrict__ out) {
    __shared__ float sh_K[Lr*5];
    __shared__ float sh_t[Lr];
    __shared__ float sh_c[Lr];
    int b = blockIdx.x;
    int j = threadIdx.x;
    int l = lengths[b];
    int base = b * Lr;

    float Ev = g_En[base + j];
    {
        const float4* Ksrc = (const float4*)(g_Kn + (size_t)base * 5);
        float4* Kdst = (float4*)sh_K;
        #pragma unroll
        for (int k = 0; k < 2; k++)
            if (j + k*1024 < Lr*5/4) Kdst[j + k*1024] = Ksrc[j + k*1024];
    }
    __syncthreads();

    float t = 1.0f, term = 0.0f;
    if (j < l) {
        t = 0.0f;
        #pragma unroll
        for (int dd = 0; dd < 5; dd++) {
            int i = j + dd - 2;
            if (i >= 0 && i < l)
                t += sh_K[i*5 + (4 - dd)];
        }
        term = Ev / ((float)l * t);
    }
    sh_t[j] = t;
    sh_c[j] = term;
    __syncthreads();

    if (j < l) {
        float rt = 1.0f / sh_t[j];
        float* Po = out + (size_t)b * Lr * Lr + (size_t)j * Lr;
        #pragma unroll
        for (int d = 0; d < 5; d++) {
            int jj = j + d - 2;
            if (jj >= 0 && jj < l)
                Po[jj] = sh_K[j*5 + d] * sh_t[jj] * rt;
        }
    }

    #pragma unroll
    for (int s = 512; s; s >>= 1) {
        if (j < s) sh_c[j] += sh_c[j + s];
        __syncthreads();
    }
    if (j == 0) out[(size_t)Br * Lr * Lr + b] = sh_c[0];
}

extern "C" void kernel_launch(void* const* d_in, const int* in_sizes, int n_in,
                              void* d_out, int out_size) {
    const float* m1      = (const float*)d_in[0];
    const float* m2      = (const float*)d_in[1];
    const int*   lengths = (const int*)d_in[2];
    float* out = (float*)d_out;

    kband<<<Br*64, 512>>>(m1, m2, lengths);   // fused-norm band, lane-parallel tail
    ktc<<<Br, 1024>>>(lengths, out);          // verified R12 epilogue
}